// round 16
// baseline (speedup 1.0000x reference)
#include <cuda_runtime.h>
#include <cuda_bf16.h>
#include <cstdint>

// ---------------------------------------------------------------------------
#define NB   32
#define C    1024
#define S    1024
#define BM   128
#define BN   128
#define BKB  128                      // K-chunk in BYTES (=128 int8 elems)
#define NCHUNK (S / BKB)              // 8
#define TILES_PER_BATCH 36
#define NBLK2 (NB * TILES_PER_BATCH)  // 1152
#define GRID2 (NBLK2 / 2)             // 576 blocks, 2 tiles each (chained)
#define TPB  256
#define STAGES 3
#define TILE_BYTES (BM * BKB)         // 16384
#define STAGE_BYTES (2 * TILE_BYTES)
#define DSMEM_BYTES (STAGES * STAGE_BYTES)   // 98304
#define TOTCH (2 * NCHUNK)            // 16 chunks across the 2 chained tiles

// Scratch
__device__ int8_t g_xq[(size_t)NB * C * S];
__device__ float  g_scale[NB * C];
__device__ float  g_partials[NBLK2];
__device__ int    g_count;            // zero-init; self-resets each run

// ---------------------------------------------------------------------------
__device__ __forceinline__ void cp_async16(uint32_t smem_addr, const void* gptr) {
    asm volatile("cp.async.cg.shared.global [%0], [%1], 16;" :: "r"(smem_addr), "l"(gptr));
}
#define CP_COMMIT() asm volatile("cp.async.commit_group;" ::: "memory")
#define CP_WAIT(n)  asm volatile("cp.async.wait_group %0;" :: "n"(n) : "memory")

__device__ __forceinline__ void ldm_x4(uint32_t& r0, uint32_t& r1, uint32_t& r2, uint32_t& r3,
                                       uint32_t addr) {
    asm volatile("ldmatrix.sync.aligned.m8n8.x4.shared.b16 {%0,%1,%2,%3}, [%4];\n"
                 : "=r"(r0), "=r"(r1), "=r"(r2), "=r"(r3) : "r"(addr));
}

__device__ __forceinline__ void mma16832_s8(int* d, const uint32_t* a, const uint32_t* b) {
    asm volatile("mma.sync.aligned.m16n8k32.row.col.s32.s8.s8.s32 "
                 "{%0,%1,%2,%3}, {%4,%5,%6,%7}, {%8,%9}, {%0,%1,%2,%3};\n"
                 : "+r"(d[0]), "+r"(d[1]), "+r"(d[2]), "+r"(d[3])
                 : "r"(a[0]), "r"(a[1]), "r"(a[2]), "r"(a[3]), "r"(b[0]), "r"(b[1]));
}

__device__ __forceinline__ uint32_t swzB(int row, int byteoff) {
    uint32_t chunk = (uint32_t)(byteoff >> 4);
    return (uint32_t)(row * 128) + ((chunk ^ ((uint32_t)row & 7u)) << 4);
}

// saturating s8 pack: w = a3:a2:a1:a0
__device__ __forceinline__ uint32_t pack_sat_s8(int a0, int a1, int a2, int a3) {
    uint32_t t, w;
    asm("cvt.pack.sat.s8.s32.b32 %0, %1, %2, 0;"  : "=r"(t) : "r"(a1), "r"(a0));
    asm("cvt.pack.sat.s8.s32.b32 %0, %1, %2, %3;" : "=r"(w) : "r"(a3), "r"(a2), "r"(t));
    return w;
}

__device__ __forceinline__ float4 ldcs4(const float4* p) {
    float4 v;
    asm volatile("ld.global.cs.v4.f32 {%0,%1,%2,%3}, [%4];"
                 : "=f"(v.x), "=f"(v.y), "=f"(v.z), "=f"(v.w) : "l"(p));
    return v;
}

// ---------------------------------------------------------------------------
// Kernel 1: normalize + int8 quantize — one warp per row; sigma-based scale
// with HW saturation (q = sat8(rint(xc*127/(4*sigma)))).
// ---------------------------------------------------------------------------
__global__ __launch_bounds__(256) void normalize_kernel(const float* __restrict__ x) {
    const int wid  = threadIdx.x >> 5;
    const int lane = threadIdx.x & 31;
    const int row  = blockIdx.x * 8 + wid;
    const size_t base = (size_t)row * S;
    const float4* in4 = reinterpret_cast<const float4*>(x + base);

    float4 v[8];
    float s = 0.f, ss = 0.f;
    #pragma unroll
    for (int i = 0; i < 8; i++) {
        v[i] = ldcs4(in4 + lane + 32 * i);
        s  += v[i].x + v[i].y + v[i].z + v[i].w;
        ss += v[i].x * v[i].x + v[i].y * v[i].y + v[i].z * v[i].z + v[i].w * v[i].w;
    }
    #pragma unroll
    for (int o = 16; o; o >>= 1) {
        s  += __shfl_xor_sync(0xFFFFFFFFu, s,  o);
        ss += __shfl_xor_sync(0xFFFFFFFFu, ss, o);
    }
    const float mean = s * (1.0f / S);
    const float rss  = fmaxf(ss - s * mean, 1e-30f);

    const float inv_nrm = 1.0f / (sqrtf(rss) + 1e-8f);
    const float qmul = 1016.0f * rsqrtf(rss);          // 127/(4*sigma)
    if (lane == 0) g_scale[row] = sqrtf(rss) * inv_nrm * (1.0f / 1016.0f);

    uint32_t* out = reinterpret_cast<uint32_t*>(g_xq + base);
    #pragma unroll
    for (int i = 0; i < 8; i++) {
        int a0 = __float2int_rn((v[i].x - mean) * qmul);
        int a1 = __float2int_rn((v[i].y - mean) * qmul);
        int a2 = __float2int_rn((v[i].z - mean) * qmul);
        int a3 = __float2int_rn((v[i].w - mean) * qmul);
        out[lane + 32 * i] = pack_sat_s8(a0, a1, a2, a3);
    }
}

// ---------------------------------------------------------------------------
// Kernel 2: int8 Gram. Each block chains TWO tiles (bx, bx+GRID2) with one
// continuous 3-stage cp.async pipeline across the tile boundary — removes the
// second tile's prologue stall and halves wave count. Per-tile epilogue with
// per-row scales; last-block final reduction.
// ---------------------------------------------------------------------------
__global__ __launch_bounds__(TPB, 2) void gram_abs_kernel(float* __restrict__ outp) {
    extern __shared__ __align__(128) char dsmem[];
    __shared__ float sScA[2][BM];
    __shared__ float sScB[2][BN];
    __shared__ float s_red[8];
    __shared__ int   s_last;

    const int tid  = threadIdx.x;
    const int wid  = tid >> 5;
    const int lane = tid & 31;
    const int warp_m = wid & 1;            // 2 x 64 rows
    const int warp_n = wid >> 1;           // 4 x 32 cols

    // decode both chained tiles
    int tiA[2], tjA[2], batchA[2];
    bool diagA[2];
    #pragma unroll
    for (int tt = 0; tt < 2; tt++) {
        const int idx = blockIdx.x + tt * GRID2;
        batchA[tt] = idx / TILES_PER_BATCH;
        int t = idx % TILES_PER_BATCH;
        int ti = 0;
        while (t >= 8 - ti) { t -= 8 - ti; ti++; }
        tiA[tt] = ti;
        tjA[tt] = ti + t;
        diagA[tt] = (ti == tjA[tt]);
    }

    // stage both tiles' row scales
    if (tid < BM) {
        sScA[0][tid] = g_scale[batchA[0] * C + tiA[0] * BM + tid];
        sScA[1][tid] = g_scale[batchA[1] * C + tiA[1] * BM + tid];
    } else {
        const int j = tid - BM;
        sScB[0][j] = g_scale[batchA[0] * C + tjA[0] * BN + j];
        sScB[1][j] = g_scale[batchA[1] * C + tjA[1] * BN + j];
    }

    const uint32_t smem_base = (uint32_t)__cvta_generic_to_shared(dsmem);

    // load chunk g (0..15): tile g>>3, local chunk g&7, stage g%3
    auto load_chunk = [&](int g) {
        const int tt  = g >> 3;
        const int k0  = (g & 7) * BKB;
        const uint32_t sA = smem_base + (g % STAGES) * STAGE_BYTES;
        const int8_t* gA = g_xq + ((size_t)batchA[tt] * C + tiA[tt] * BM) * S;
        #pragma unroll
        for (int it = 0; it < 4; it++) {
            int idx = it * TPB + tid;
            int r   = idx >> 3;
            int c16 = idx & 7;
            cp_async16(sA + swzB(r, c16 * 16), gA + (size_t)r * S + k0 + c16 * 16);
        }
        if (!diagA[tt]) {
            const uint32_t sB = sA + TILE_BYTES;
            const int8_t* gB = g_xq + ((size_t)batchA[tt] * C + tjA[tt] * BN) * S;
            #pragma unroll
            for (int it = 0; it < 4; it++) {
                int idx = it * TPB + tid;
                int r   = idx >> 3;
                int c16 = idx & 7;
                cp_async16(sB + swzB(r, c16 * 16), gB + (size_t)r * S + k0 + c16 * 16);
            }
        }
    };

    const int a_row  = warp_m * 64 + (lane & 15);
    const int a_colB = (lane >> 4) * 16;
    const int b_row  = warp_n * 32 + (lane & 7) + ((lane >> 4) << 3);
    const int b_colB = ((lane >> 3) & 1) * 16;

    int acc[4][4][4];
    #pragma unroll
    for (int i = 0; i < 4; i++)
        #pragma unroll
        for (int j = 0; j < 4; j++)
            #pragma unroll
            for (int r = 0; r < 4; r++) acc[i][j][r] = 0;

    load_chunk(0); CP_COMMIT();
    load_chunk(1); CP_COMMIT();

    float bsum0 = 0.0f;   // tile-0 partial (tid 0 only, written at end)

    for (int g = 0; g < TOTCH; g++) {
        const int tt = g >> 3;
        const bool diag = diagA[tt];
        const bool dead_warp = diag && (warp_m == 1) && (warp_n < 2);
        CP_WAIT(1);
        __syncthreads();   // chunk g resident; all warps done with stage g-1

        if (g + 2 < TOTCH) {
            load_chunk(g + 2);
            CP_COMMIT();
        }

        if (!dead_warp) {
            const uint32_t sA = smem_base + (g % STAGES) * STAGE_BYTES;
            const uint32_t sB = diag ? sA : (sA + TILE_BYTES);
            #pragma unroll
            for (int kk = 0; kk < 4; kk++) {
                const int kb = kk * 32;
                uint32_t a[4][4];
                #pragma unroll
                for (int mf = 0; mf < 4; mf++) {
                    uint32_t addr = sA + swzB(a_row + mf * 16, kb + a_colB);
                    ldm_x4(a[mf][0], a[mf][1], a[mf][2], a[mf][3], addr);
                }
                uint32_t b[4][2];
                {
                    uint32_t addr0 = sB + swzB(b_row, kb + b_colB);
                    ldm_x4(b[0][0], b[0][1], b[1][0], b[1][1], addr0);
                    uint32_t addr1 = sB + swzB(b_row + 16, kb + b_colB);
                    ldm_x4(b[2][0], b[2][1], b[3][0], b[3][1], addr1);
                }
                #pragma unroll
                for (int mf = 0; mf < 4; mf++)
                    #pragma unroll
                    for (int nf = 0; nf < 4; nf++)
                        mma16832_s8(acc[mf][nf], a[mf], b[nf]);
            }
        }

        // tile boundary: epilogue for tile tt, reset acc
        if ((g & 7) == 7) {
            const int ti = tiA[tt], tj = tjA[tt];
            const int groupID = lane >> 2;
            const int tid4    = lane & 3;
            float lsum = 0.0f;
            if (!diag) {
                #pragma unroll
                for (int mf = 0; mf < 4; mf++) {
                    const int li0 = warp_m * 64 + mf * 16 + groupID;
                    const float sa0 = sScA[tt][li0];
                    const float sa1 = sScA[tt][li0 + 8];
                    #pragma unroll
                    for (int nf = 0; nf < 4; nf++) {
                        const int lj = warp_n * 32 + nf * 8 + tid4 * 2;
                        const float sb0 = sScB[tt][lj];
                        const float sb1 = sScB[tt][lj + 1];
                        lsum += fabsf((float)acc[mf][nf][0] * sa0 * sb0);
                        lsum += fabsf((float)acc[mf][nf][1] * sa0 * sb1);
                        lsum += fabsf((float)acc[mf][nf][2] * sa1 * sb0);
                        lsum += fabsf((float)acc[mf][nf][3] * sa1 * sb1);
                    }
                }
            } else if (!dead_warp) {
                #pragma unroll
                for (int mf = 0; mf < 4; mf++) {
                    const int li0 = warp_m * 64 + mf * 16 + groupID;
                    const int li1 = li0 + 8;
                    const float sa0 = sScA[tt][li0];
                    const float sa1 = sScA[tt][li1];
                    const int gi0 = ti * BM + li0;
                    const int gi1 = ti * BM + li1;
                    #pragma unroll
                    for (int nf = 0; nf < 4; nf++) {
                        const int lj = warp_n * 32 + nf * 8 + tid4 * 2;
                        const int gj = tj * BN + lj;
                        const float sb0 = sScB[tt][lj];
                        const float sb1 = sScB[tt][lj + 1];
                        if (gj     > gi0) lsum += fabsf((float)acc[mf][nf][0] * sa0 * sb0);
                        if (gj + 1 > gi0) lsum += fabsf((float)acc[mf][nf][1] * sa0 * sb1);
                        if (gj     > gi1) lsum += fabsf((float)acc[mf][nf][2] * sa1 * sb0);
                        if (gj + 1 > gi1) lsum += fabsf((float)acc[mf][nf][3] * sa1 * sb1);
                    }
                }
            }
            #pragma unroll
            for (int o = 16; o; o >>= 1) lsum += __shfl_xor_sync(0xFFFFFFFFu, lsum, o);

            __syncthreads();                 // s_red free (prev tile / prev use done)
            if (lane == 0) s_red[wid] = lsum;
            __syncthreads();
            if (tid == 0) {
                float bs = 0.f;
                #pragma unroll
                for (int w = 0; w < 8; w++) bs += s_red[w];
                if (tt == 0) bsum0 = bs;
                else         g_partials[blockIdx.x + GRID2] = bs;
            }

            // reset acc for the next tile
            #pragma unroll
            for (int i = 0; i < 4; i++)
                #pragma unroll
                for (int j = 0; j < 4; j++)
                    #pragma unroll
                    for (int r = 0; r < 4; r++) acc[i][j][r] = 0;
        }
    }

    if (tid == 0) {
        g_partials[blockIdx.x] = bsum0;
        __threadfence();
        int ticket = atomicAdd(&g_count, 1);
        s_last = (ticket == GRID2 - 1) ? 1 : 0;
    }
    __syncthreads();

    // Last block reduces all 1152 partials (same order as before)
    if (s_last) {
        __threadfence();
        float s = 0.0f;
        for (int i = tid; i < NBLK2; i += TPB) s += g_partials[i];
        #pragma unroll
        for (int o = 16; o; o >>= 1) s += __shfl_xor_sync(0xFFFFFFFFu, s, o);
        if (lane == 0) s_red[wid] = s;
        __syncthreads();
        if (tid == 0) {
            float tot = 0.f;
            #pragma unroll
            for (int w = 0; w < 8; w++) tot += s_red[w];
            const float comb = (float)C * (C - 1) * 0.5f;
            outp[0] = tot / (comb * (float)NB);
            g_count = 0;                       // self-reset for graph replay
        }
    }
}

// ---------------------------------------------------------------------------
extern "C" void kernel_launch(void* const* d_in, const int* in_sizes, int n_in,
                              void* d_out, int out_size) {
    const float* x = (const float*)d_in[0];
    float* out = (float*)d_out;

    cudaFuncSetAttribute(gram_abs_kernel,
                         cudaFuncAttributeMaxDynamicSharedMemorySize, DSMEM_BYTES);

    normalize_kernel<<<NB * C / 8, 256>>>(x);
    gram_abs_kernel<<<GRID2, TPB, DSMEM_BYTES>>>(out);
}

// round 17
// speedup vs baseline: 1.0549x; 1.0549x over previous
#include <cuda_runtime.h>
#include <cuda_bf16.h>
#include <cstdint>

// ---------------------------------------------------------------------------
#define NB   32
#define C    1024
#define S    1024
#define BM   128
#define BN   128
#define BKB  128                      // K-chunk in BYTES (=128 int8 elems)
#define NCHUNK (S / BKB)              // 8
#define TILES_PER_BATCH 36
#define NBLK2 (NB * TILES_PER_BATCH)  // 1152
#define TPB  256
#define STAGES 3
#define TILE_BYTES (BM * BKB)         // 16384
#define STAGE_BYTES (2 * TILE_BYTES)
#define DSMEM_BYTES (STAGES * STAGE_BYTES)   // 98304

// Scratch
__device__ int8_t g_xq[(size_t)NB * C * S];
__device__ float  g_scale[NB * C];
__device__ float  g_partials[NBLK2];
__device__ int    g_count;            // zero-init; self-resets each run

// ---------------------------------------------------------------------------
__device__ __forceinline__ void cp_async16(uint32_t smem_addr, const void* gptr) {
    asm volatile("cp.async.cg.shared.global [%0], [%1], 16;" :: "r"(smem_addr), "l"(gptr));
}
#define CP_COMMIT() asm volatile("cp.async.commit_group;" ::: "memory")
#define CP_WAIT(n)  asm volatile("cp.async.wait_group %0;" :: "n"(n) : "memory")

__device__ __forceinline__ void ldm_x4(uint32_t& r0, uint32_t& r1, uint32_t& r2, uint32_t& r3,
                                       uint32_t addr) {
    asm volatile("ldmatrix.sync.aligned.m8n8.x4.shared.b16 {%0,%1,%2,%3}, [%4];\n"
                 : "=r"(r0), "=r"(r1), "=r"(r2), "=r"(r3) : "r"(addr));
}

__device__ __forceinline__ void mma16832_s8(int* d, const uint32_t* a, const uint32_t* b) {
    asm volatile("mma.sync.aligned.m16n8k32.row.col.s32.s8.s8.s32 "
                 "{%0,%1,%2,%3}, {%4,%5,%6,%7}, {%8,%9}, {%0,%1,%2,%3};\n"
                 : "+r"(d[0]), "+r"(d[1]), "+r"(d[2]), "+r"(d[3])
                 : "r"(a[0]), "r"(a[1]), "r"(a[2]), "r"(a[3]), "r"(b[0]), "r"(b[1]));
}

__device__ __forceinline__ uint32_t swzB(int row, int byteoff) {
    uint32_t chunk = (uint32_t)(byteoff >> 4);
    return (uint32_t)(row * 128) + ((chunk ^ ((uint32_t)row & 7u)) << 4);
}

// saturating s8 pack: w = a3:a2:a1:a0
__device__ __forceinline__ uint32_t pack_sat_s8(int a0, int a1, int a2, int a3) {
    uint32_t t, w;
    asm("cvt.pack.sat.s8.s32.b32 %0, %1, %2, 0;"  : "=r"(t) : "r"(a1), "r"(a0));
    asm("cvt.pack.sat.s8.s32.b32 %0, %1, %2, %3;" : "=r"(w) : "r"(a3), "r"(a2), "r"(t));
    return w;
}

__device__ __forceinline__ float4 ldcs4(const float4* p) {
    float4 v;
    asm volatile("ld.global.cs.v4.f32 {%0,%1,%2,%3}, [%4];"
                 : "=f"(v.x), "=f"(v.y), "=f"(v.z), "=f"(v.w) : "l"(p));
    return v;
}

// ---------------------------------------------------------------------------
// Kernel 1: normalize + int8 quantize — one warp per row; sigma-based scale
// with HW saturation (q = sat8(rint(xc*127/(4*sigma)))).
// ---------------------------------------------------------------------------
__global__ __launch_bounds__(256) void normalize_kernel(const float* __restrict__ x) {
    const int wid  = threadIdx.x >> 5;
    const int lane = threadIdx.x & 31;
    const int row  = blockIdx.x * 8 + wid;
    const size_t base = (size_t)row * S;
    const float4* in4 = reinterpret_cast<const float4*>(x + base);

    float4 v[8];
    float s = 0.f, ss = 0.f;
    #pragma unroll
    for (int i = 0; i < 8; i++) {
        v[i] = ldcs4(in4 + lane + 32 * i);     // evict-first: preserve L2 for g_xq
        s  += v[i].x + v[i].y + v[i].z + v[i].w;
        ss += v[i].x * v[i].x + v[i].y * v[i].y + v[i].z * v[i].z + v[i].w * v[i].w;
    }
    #pragma unroll
    for (int o = 16; o; o >>= 1) {
        s  += __shfl_xor_sync(0xFFFFFFFFu, s,  o);
        ss += __shfl_xor_sync(0xFFFFFFFFu, ss, o);
    }
    const float mean = s * (1.0f / S);
    const float rss  = fmaxf(ss - s * mean, 1e-30f);

    const float inv_nrm = 1.0f / (sqrtf(rss) + 1e-8f);
    const float qmul = 1016.0f * rsqrtf(rss);          // 127/(4*sigma)
    if (lane == 0) g_scale[row] = sqrtf(rss) * inv_nrm * (1.0f / 1016.0f);

    uint32_t* out = reinterpret_cast<uint32_t*>(g_xq + base);
    #pragma unroll
    for (int i = 0; i < 8; i++) {
        int a0 = __float2int_rn((v[i].x - mean) * qmul);
        int a1 = __float2int_rn((v[i].y - mean) * qmul);
        int a2 = __float2int_rn((v[i].z - mean) * qmul);
        int a3 = __float2int_rn((v[i].w - mean) * qmul);
        out[lane + 32 * i] = pack_sat_s8(a0, a1, a2, a3);
    }
}

// ---------------------------------------------------------------------------
// Kernel 2: int8 Gram tile (8 warps of 64x32), 3-stage cp.async pipeline with
// de-burst load issue (A loads after kk=0, B loads after kk=1), single sync
// per chunk, diagonal B-elision, dead-warp elision, factored per-row-scale
// epilogue, masked |.| sum, last-block final reduction.
// ---------------------------------------------------------------------------
__global__ __launch_bounds__(TPB, 2) void gram_abs_kernel(float* __restrict__ outp) {
    extern __shared__ __align__(128) char dsmem[];
    __shared__ float sScA[BM];
    __shared__ float sScB[BN];
    __shared__ float s_red[8];
    __shared__ int   s_last;

    const int tid  = threadIdx.x;
    const int wid  = tid >> 5;
    const int lane = tid & 31;
    const int warp_m = wid & 1;            // 2 x 64 rows
    const int warp_n = wid >> 1;           // 4 x 32 cols

    const int bx = blockIdx.x;
    const int batch = bx / TILES_PER_BATCH;
    int t = bx % TILES_PER_BATCH;
    int ti = 0;
    while (t >= 8 - ti) { t -= 8 - ti; ti++; }
    const int tj = ti + t;
    const bool diag = (ti == tj);
    const bool dead_warp = diag && (warp_m == 1) && (warp_n < 2);

    const int8_t* gA = g_xq + ((size_t)batch * C + ti * BM) * S;
    const int8_t* gB = g_xq + ((size_t)batch * C + tj * BN) * S;

    if (tid < BM) sScA[tid] = g_scale[batch * C + ti * BM + tid];
    else          sScB[tid - BM] = g_scale[batch * C + tj * BN + (tid - BM)];

    const uint32_t smem_base = (uint32_t)__cvta_generic_to_shared(dsmem);

    auto load_A = [&](int cch, int stage) {
        const int k0 = cch * BKB;
        const uint32_t sA = smem_base + stage * STAGE_BYTES;
        #pragma unroll
        for (int it = 0; it < 4; it++) {
            int idx = it * TPB + tid;
            int r   = idx >> 3;
            int c16 = idx & 7;
            cp_async16(sA + swzB(r, c16 * 16), gA + (size_t)r * S + k0 + c16 * 16);
        }
    };
    auto load_B = [&](int cch, int stage) {
        const int k0 = cch * BKB;
        const uint32_t sB = smem_base + stage * STAGE_BYTES + TILE_BYTES;
        #pragma unroll
        for (int it = 0; it < 4; it++) {
            int idx = it * TPB + tid;
            int r   = idx >> 3;
            int c16 = idx & 7;
            cp_async16(sB + swzB(r, c16 * 16), gB + (size_t)r * S + k0 + c16 * 16);
        }
    };

    const int a_row  = warp_m * 64 + (lane & 15);
    const int a_colB = (lane >> 4) * 16;
    const int b_row  = warp_n * 32 + (lane & 7) + ((lane >> 4) << 3);
    const int b_colB = ((lane >> 3) & 1) * 16;

    int acc[4][4][4];
    #pragma unroll
    for (int i = 0; i < 4; i++)
        #pragma unroll
        for (int j = 0; j < 4; j++)
            #pragma unroll
            for (int r = 0; r < 4; r++) acc[i][j][r] = 0;

    load_A(0, 0); if (!diag) load_B(0, 0); CP_COMMIT();
    load_A(1, 1); if (!diag) load_B(1, 1); CP_COMMIT();

    for (int cch = 0; cch < NCHUNK; cch++) {
        const int stage = cch % STAGES;
        CP_WAIT(1);
        __syncthreads();   // chunk cch resident; compute(cch-1) done by all warps

        const bool more = (cch + 2 < NCHUNK);
        const int st2 = (cch + 2) % STAGES;
        const uint32_t sA = smem_base + stage * STAGE_BYTES;
        const uint32_t sB = diag ? sA : (sA + TILE_BYTES);

        auto kk_step = [&](int kk) {
            const int kb = kk * 32;
            uint32_t a[4][4];
            #pragma unroll
            for (int mf = 0; mf < 4; mf++) {
                uint32_t addr = sA + swzB(a_row + mf * 16, kb + a_colB);
                ldm_x4(a[mf][0], a[mf][1], a[mf][2], a[mf][3], addr);
            }
            uint32_t b[4][2];
            {
                uint32_t addr0 = sB + swzB(b_row, kb + b_colB);
                ldm_x4(b[0][0], b[0][1], b[1][0], b[1][1], addr0);
                uint32_t addr1 = sB + swzB(b_row + 16, kb + b_colB);
                ldm_x4(b[2][0], b[2][1], b[3][0], b[3][1], addr1);
            }
            #pragma unroll
            for (int mf = 0; mf < 4; mf++)
                #pragma unroll
                for (int nf = 0; nf < 4; nf++)
                    mma16832_s8(acc[mf][nf], a[mf], b[nf]);
        };

        // de-burst: A loads after kk=0, B loads after kk=1, commit once
        if (!dead_warp) kk_step(0);
        if (more) load_A(cch + 2, st2);
        if (!dead_warp) kk_step(1);
        if (more) {
            if (!diag) load_B(cch + 2, st2);
            CP_COMMIT();
        }
        if (!dead_warp) { kk_step(2); kk_step(3); }
        // no trailing sync: top-of-loop sync of iter cch+1 protects stage reuse
    }

    // Epilogue. Scales are positive, so |acc*sa*sb| = (|acc|*sb)*sa and the
    // sa multiply factors out of the nf loop.
    const int groupID = lane >> 2;
    const int tid4    = lane & 3;
    float lsum = 0.0f;
    if (!diag) {
        #pragma unroll
        for (int mf = 0; mf < 4; mf++) {
            const int li0 = warp_m * 64 + mf * 16 + groupID;
            float r0 = 0.f, r1 = 0.f;      // row-partials before sa multiply
            #pragma unroll
            for (int nf = 0; nf < 4; nf++) {
                const int lj = warp_n * 32 + nf * 8 + tid4 * 2;
                const float sb0 = sScB[lj];
                const float sb1 = sScB[lj + 1];
                r0 += fabsf((float)acc[mf][nf][0]) * sb0;
                r0 += fabsf((float)acc[mf][nf][1]) * sb1;
                r1 += fabsf((float)acc[mf][nf][2]) * sb0;
                r1 += fabsf((float)acc[mf][nf][3]) * sb1;
            }
            lsum += r0 * sScA[li0] + r1 * sScA[li0 + 8];
        }
        #pragma unroll
        for (int o = 16; o; o >>= 1) lsum += __shfl_xor_sync(0xFFFFFFFFu, lsum, o);
    } else if (!dead_warp) {
        #pragma unroll
        for (int mf = 0; mf < 4; mf++) {
            const int li0 = warp_m * 64 + mf * 16 + groupID;
            const int li1 = li0 + 8;
            const float sa0 = sScA[li0];
            const float sa1 = sScA[li1];
            const int gi0 = ti * BM + li0;
            const int gi1 = ti * BM + li1;
            #pragma unroll
            for (int nf = 0; nf < 4; nf++) {
                const int lj = warp_n * 32 + nf * 8 + tid4 * 2;
                const int gj = tj * BN + lj;
                const float sb0 = sScB[lj];
                const float sb1 = sScB[lj + 1];
                if (gj     > gi0) lsum += fabsf((float)acc[mf][nf][0] * sa0 * sb0);
                if (gj + 1 > gi0) lsum += fabsf((float)acc[mf][nf][1] * sa0 * sb1);
                if (gj     > gi1) lsum += fabsf((float)acc[mf][nf][2] * sa1 * sb0);
                if (gj + 1 > gi1) lsum += fabsf((float)acc[mf][nf][3] * sa1 * sb1);
            }
        }
        #pragma unroll
        for (int o = 16; o; o >>= 1) lsum += __shfl_xor_sync(0xFFFFFFFFu, lsum, o);
    }

    if (lane == 0) s_red[wid] = lsum;
    __syncthreads();
    if (tid == 0) {
        float bsum = 0.f;
        #pragma unroll
        for (int w = 0; w < 8; w++) bsum += s_red[w];
        g_partials[bx] = bsum;
        __threadfence();
        int ticket = atomicAdd(&g_count, 1);
        s_last = (ticket == NBLK2 - 1) ? 1 : 0;
    }
    __syncthreads();

    // Last block reduces all partials (same order as the old finalize kernel)
    if (s_last) {
        __threadfence();
        float s = 0.0f;
        for (int i = tid; i < NBLK2; i += TPB) s += g_partials[i];
        #pragma unroll
        for (int o = 16; o; o >>= 1) s += __shfl_xor_sync(0xFFFFFFFFu, s, o);
        if (lane == 0) s_red[wid] = s;
        __syncthreads();
        if (tid == 0) {
            float tot = 0.f;
            #pragma unroll
            for (int w = 0; w < 8; w++) tot += s_red[w];
            const float comb = (float)C * (C - 1) * 0.5f;
            outp[0] = tot / (comb * (float)NB);
            g_count = 0;                       // self-reset for graph replay
        }
    }
}

// ---------------------------------------------------------------------------
extern "C" void kernel_launch(void* const* d_in, const int* in_sizes, int n_in,
                              void* d_out, int out_size) {
    const float* x = (const float*)d_in[0];
    float* out = (float*)d_out;

    cudaFuncSetAttribute(gram_abs_kernel,
                         cudaFuncAttributeMaxDynamicSharedMemorySize, DSMEM_BYTES);

    normalize_kernel<<<NB * C / 8, 256>>>(x);
    gram_abs_kernel<<<NBLK2, TPB, DSMEM_BYTES>>>(out);
}